// round 17
// baseline (speedup 1.0000x reference)
#include <cuda_runtime.h>
#include <cstdint>

#define BATCH  16
#define MAXLEN 128
#define NTOK   (BATCH * MAXLEN)   // 2048
#define VOCAB  32128
#define V4     (VOCAB / 4)        // 8032
#define NSLICE 8                  // vocab slices per token
#define V4S    (V4 / NSLICE)      // 1004 float4 per slice per array
#define NITEM  (NTOK * NSLICE)    // 16384 work items
#define EMB    768
#define EMB4   (EMB / 4)          // 192
#define NBLK   1184               // 148 SMs x 8 resident blocks: one wave

// Scratch (device globals: allocation-free). g_ctr is reset by k_reset each
// launch; g_key/g_ticket are zero-init at load and self-cleaned by the
// finishing block every invocation -> deterministic across graph replays.
__device__ unsigned            g_ctr;
__device__ unsigned long long  g_key[NTOK];
__device__ int                 g_ticket[NTOK];

// monotone f32 -> u32 map: a > b  <=>  monotone(a) > monotone(b)
__device__ __forceinline__ unsigned monotone_f32(float f) {
    unsigned u = __float_as_uint(f);
    return (u & 0x80000000u) ? ~u : (u | 0x80000000u);
}

// ---------------------------------------------------------------------------
// Bit-exact replication of:
//   coord = jnp.linspace(-1, 1, size)[h]
//     JAX linspace (num>1): s = iota(f32 h)/f32(div); out = start*(1-s)+stop*s,
//     endpoint appended exactly as `stop`.
//   ix = ((coord + 1.0)*size - 1.0)/2.0 ;  round half-even ; clip [0, size-1]
// All ops forced to un-fused f32. (EMB column map is provably identity —
// validated by the rel_err=0 scalar-path runs — so only the vocab row uses
// this.)
// ---------------------------------------------------------------------------
__device__ __forceinline__ int nearest_idx_rep(int h, int size) {
    float coord;
    if (h == size - 1) {
        coord = 1.0f;                                     // endpoint set to stop
    } else {
        float s = __fdiv_rn((float)h, (float)(size - 1)); // iota/div
        float t = __fsub_rn(1.0f, s);                     // (1 - step)
        float a = __fmul_rn(-1.0f, t);                    // start*(1-step)
        coord   = __fadd_rn(a, s);                        // + stop*step
    }
    float u1 = __fadd_rn(coord, 1.0f);
    float u2 = __fmul_rn(u1, (float)size);
    float u3 = __fsub_rn(u2, 1.0f);
    float ix = __fdiv_rn(u3, 2.0f);
    float r  = rintf(ix);                                 // round half-to-even
    r = fminf(fmaxf(r, 0.0f), (float)(size - 1));
    return (int)r;
}

__global__ void k_reset() { g_ctr = 0u; }

// ---------------------------------------------------------------------------
// Persistent work-stealing kernel. 1184 resident blocks pull items from a
// global counter. Item = (token, slice): token tok = item/8 streams vocab
// slice [slice*V/8, (slice+1)*V/8) of (logits+gumbel) and combines into
// g_key[tok] via atomicMax of (monotone(val)<<32 | ~idx)  ==> max value,
// min index on ties = jnp.argmax first-occurrence. The 8th-arriving block
// (ticket) decodes the winner, self-cleans scratch, and runs the epilogue.
// Dead tokens (mask==0: inputs_embeds row is zeroed in the reference, hot
// unused) are skipped; their slice-0 item emits the psg-only output row.
//
// Passage bookkeeping (per batch, mask/psg rows L2-hot):
//   psg_r    = roll(psg_ids, 1) with BOS=1
//   extr[k]  = (1 - mask[L-1-k]) * psg_r[k]
//   trunc[k] = extr[(k - sum(mask)) mod L]
//   flag[k]  = any_{i<=k} trunc[i] != 0  -> rb = flag[j] ? trunc[j] : -1
// Output: out[tok,:] = (ra>=0 ? WE[ra,:] : 0) + (rb>=0 ? WE[rb,:] : 0)
// ---------------------------------------------------------------------------
struct SmemT {
    int   item;
    int   mask[MAXLEN];
    int   extr[MAXLEN];
    int   red[4];
    int   rb, ra, fin;
    float sv[8];
    int   si[8];
};

// bookkeeping + dual gather for token `tok` with vocab row `ra` (-1 = none).
// Must be executed by ALL 256 threads of the block (contains barriers).
__device__ __forceinline__ void epilogue(
    int tok, int ra, SmemT* sm,
    const int* __restrict__ mask, const int* __restrict__ psg,
    const float4* __restrict__ we4, float4* __restrict__ out4, int tid)
{
    const int b = tok >> 7;
    const int j = tok & (MAXLEN - 1);
    int m = 0, pj = 0;
    if (tid < MAXLEN) {
        m  = __ldg(&mask[b * MAXLEN + tid]);
        pj = (tid == 0) ? 1 : __ldg(&psg[b * MAXLEN + tid - 1]);
        sm->mask[tid] = m;
    }
    __syncthreads();

    if (tid < MAXLEN) {
        sm->extr[tid] = (1 - sm->mask[MAXLEN - 1 - tid]) * pj;
        unsigned wsum = __reduce_add_sync(0xffffffffu, (unsigned)m);
        if ((tid & 31) == 0) sm->red[tid >> 5] = (int)wsum;
    }
    __syncthreads();

    if (tid < MAXLEN) {
        int shifts = sm->red[0] + sm->red[1] + sm->red[2] + sm->red[3];
        int pos    = (tid - shifts + MAXLEN) & (MAXLEN - 1);
        int tr     = sm->extr[pos];
        if (tid == j) sm->rb = tr;               // provisional: trunc[j]
        int key = (tr != 0) ? tid : MAXLEN;
        unsigned wmin = __reduce_min_sync(0xffffffffu, (unsigned)key);
        if ((tid & 31) == 0) sm->red[tid >> 5] = (int)wmin;
    }
    __syncthreads();

    if (tid == 0) {
        int firstnz = min(min(sm->red[0], sm->red[1]),
                          min(sm->red[2], sm->red[3]));
        if (j < firstnz) sm->rb = -1;            // leading zeros -> no embed
    }
    __syncthreads();

    const int rb = sm->rb;
    if (tid < EMB4) {
        float4 v = make_float4(0.f, 0.f, 0.f, 0.f);
        if (ra >= 0) v = __ldg(&we4[(size_t)ra * EMB4 + tid]);
        if (rb >= 0) {
            float4 w = __ldg(&we4[(size_t)rb * EMB4 + tid]);
            v.x = __fadd_rn(v.x, w.x);
            v.y = __fadd_rn(v.y, w.y);
            v.z = __fadd_rn(v.z, w.z);
            v.w = __fadd_rn(v.w, w.w);
        }
        out4[(size_t)tok * EMB4 + tid] = v;
    }
}

__global__ __launch_bounds__(256, 8) void k_main(
    const float4* __restrict__ lg, const float4* __restrict__ gm,
    const int* __restrict__ mask, const int* __restrict__ psg,
    const float4* __restrict__ we4, float4* __restrict__ out4)
{
    __shared__ SmemT sm;
    const int tid = threadIdx.x;

    while (true) {
        if (tid == 0) sm.item = (int)atomicAdd(&g_ctr, 1u);
        __syncthreads();
        const int item = sm.item;
        __syncthreads();                 // sm.item safe for next overwrite

        if (item >= NITEM) break;        // uniform exit

        const int tok   = item >> 3;
        const int slice = item & (NSLICE - 1);
        const int mj    = __ldg(&mask[tok]);

        if (!mj) {
            // dead token: slice 0 emits the psg-only row; others skip
            if (slice == 0)
                epilogue(tok, -1, &sm, mask, psg, we4, out4, tid);
            continue;
        }

        // ---- stream this slice of (logits + gumbel) ----
        const float4* L = lg + (size_t)tok * V4 + slice * V4S;
        const float4* G = gm + (size_t)tok * V4 + slice * V4S;
        const int vbase = (slice * V4S) << 2;     // global vocab index base

        float best = -3.402823466e38f;
        int   bi   = vbase;

        #pragma unroll 4
        for (int i = tid; i < V4S; i += 256) {
            float4 a = __ldcs(&L[i]);
            float4 c = __ldcs(&G[i]);
            float v0 = __fadd_rn(a.x, c.x);
            float v1 = __fadd_rn(a.y, c.y);
            float v2 = __fadd_rn(a.z, c.z);
            float v3 = __fadd_rn(a.w, c.w);
            int base = vbase + (i << 2);
            // per-thread indices strictly increase -> '>' keeps 1st occurrence
            if (v0 > best) { best = v0; bi = base;     }
            if (v1 > best) { best = v1; bi = base + 1; }
            if (v2 > best) { best = v2; bi = base + 2; }
            if (v3 > best) { best = v3; bi = base + 3; }
        }

        // block reduce: (maxval, min-index-on-tie)
        #pragma unroll
        for (int o = 16; o > 0; o >>= 1) {
            float ov = __shfl_down_sync(0xffffffffu, best, o);
            int   oi = __shfl_down_sync(0xffffffffu, bi,   o);
            if (ov > best || (ov == best && oi < bi)) { best = ov; bi = oi; }
        }
        if ((tid & 31) == 0) { sm.sv[tid >> 5] = best; sm.si[tid >> 5] = bi; }
        __syncthreads();

        if (tid == 0) {
            best = sm.sv[0]; bi = sm.si[0];
            #pragma unroll
            for (int w = 1; w < 8; w++) {
                if (sm.sv[w] > best || (sm.sv[w] == best && sm.si[w] < bi)) {
                    best = sm.sv[w]; bi = sm.si[w];
                }
            }
            unsigned long long key =
                ((unsigned long long)monotone_f32(best) << 32) |
                (unsigned)(~(unsigned)bi);
            atomicMax(&g_key[tok], key);
            __threadfence();
            int t = atomicAdd(&g_ticket[tok], 1);
            sm.fin = (t == NSLICE - 1);          // last arrival owns epilogue
            if (sm.fin) {
                __threadfence();                 // acquire: see all 8 maxes
                unsigned long long kk = atomicExch(&g_key[tok], 0ULL);
                atomicExch(&g_ticket[tok], 0);   // self-clean for replay
                int bi_g = (int)(~(unsigned)(kk & 0xFFFFFFFFull));
                sm.ra = nearest_idx_rep(bi_g, VOCAB);
            }
        }
        __syncthreads();

        if (sm.fin)
            epilogue(tok, sm.ra, &sm, mask, psg, we4, out4, tid);
    }
}

// ---------------------------------------------------------------------------
// Entry point. Inputs (metadata order):
//   0: logits           f32 [16,128,32128]
//   1: rwrt_attn_mask   i32 [16,128]
//   2: psg_input_ids    i32 [16,128]
//   3: word_embeddings  f32 [32128,768]
//   4: gumbel_noise     f32 [16,128,32128]
// Output: f32 [16,128,768]
// ---------------------------------------------------------------------------
extern "C" void kernel_launch(void* const* d_in, const int* in_sizes, int n_in,
                              void* d_out, int out_size)
{
    const float* logits = (const float*)d_in[0];
    const int*   mask   = (const int*)  d_in[1];
    const int*   psg    = (const int*)  d_in[2];
    const float* we     = (const float*)d_in[3];
    const float* gum    = (const float*)d_in[4];

    k_reset<<<1, 1>>>();
    k_main<<<NBLK, 256>>>((const float4*)logits, (const float4*)gum,
                          mask, psg, (const float4*)we, (float4*)d_out);
}